// round 1
// baseline (speedup 1.0000x reference)
#include <cuda_runtime.h>
#include <math.h>

// Problem constants (fixed shapes for this instance)
#define NTOK   4096     // N = D*H*W
#define NHEAD  8
#define HDIM   64
#define NSAMP  27
#define CDIM   512
#define QKVW   1536     // 3*C

// -------- scratch (no allocations allowed) --------
__device__ float g_qkv[NTOK * QKVW];          // (N, 3C)  q|k|v interleaved per token
__device__ float g_off[NHEAD * NTOK * 81];    // per (h,n): 81 offset values
__device__ float g_ao [NTOK * CDIM];          // attention output (N, C)

// ============================================================
// SGEMM (NT): C[M,N] = A[M,K] @ W[N,K]^T (+ bias)
// BM=BN=128, BK=8, 256 threads, 8x8 microtile.
// Requires M,N % 128 == 0, K % 8 == 0 (true here).
// ============================================================
__global__ void __launch_bounds__(256) sgemm_nt(
    const float* __restrict__ A, const float* __restrict__ W,
    const float* __restrict__ bias, float* __restrict__ C,
    int M, int N, int K)
{
    __shared__ float As[8][128];
    __shared__ float Ws[8][128];
    const int m0 = blockIdx.y * 128;
    const int n0 = blockIdx.x * 128;
    const int tid = threadIdx.x;
    const int tx = tid & 15;       // n-dir
    const int ty = tid >> 4;       // m-dir
    const int lrow = tid >> 1;     // 0..127
    const int lk4  = (tid & 1) << 2;

    const float* Ap = A + (size_t)(m0 + lrow) * K + lk4;
    const float* Wp = W + (size_t)(n0 + lrow) * K + lk4;

    float acc[8][8];
#pragma unroll
    for (int i = 0; i < 8; i++)
#pragma unroll
        for (int j = 0; j < 8; j++) acc[i][j] = 0.f;

    for (int k0 = 0; k0 < K; k0 += 8) {
        float4 av = *(const float4*)(Ap + k0);
        float4 wv = *(const float4*)(Wp + k0);
        As[lk4 + 0][lrow] = av.x; As[lk4 + 1][lrow] = av.y;
        As[lk4 + 2][lrow] = av.z; As[lk4 + 3][lrow] = av.w;
        Ws[lk4 + 0][lrow] = wv.x; Ws[lk4 + 1][lrow] = wv.y;
        Ws[lk4 + 2][lrow] = wv.z; Ws[lk4 + 3][lrow] = wv.w;
        __syncthreads();
#pragma unroll
        for (int kk = 0; kk < 8; kk++) {
            float4 a0 = *(const float4*)&As[kk][ty * 8];
            float4 a1 = *(const float4*)&As[kk][ty * 8 + 4];
            float4 b0 = *(const float4*)&Ws[kk][tx * 8];
            float4 b1 = *(const float4*)&Ws[kk][tx * 8 + 4];
            float ar[8] = {a0.x, a0.y, a0.z, a0.w, a1.x, a1.y, a1.z, a1.w};
            float br[8] = {b0.x, b0.y, b0.z, b0.w, b1.x, b1.y, b1.z, b1.w};
#pragma unroll
            for (int i = 0; i < 8; i++)
#pragma unroll
                for (int j = 0; j < 8; j++)
                    acc[i][j] = fmaf(ar[i], br[j], acc[i][j]);
        }
        __syncthreads();
    }

    float bv[8];
#pragma unroll
    for (int j = 0; j < 8; j++) bv[j] = bias ? bias[n0 + tx * 8 + j] : 0.f;

#pragma unroll
    for (int i = 0; i < 8; i++) {
        float* Cp = C + (size_t)(m0 + ty * 8 + i) * N + n0 + tx * 8;
#pragma unroll
        for (int j = 0; j < 8; j++) Cp[j] = acc[i][j] + bv[j];
    }
}

// ============================================================
// Offsets: out[(h*N+n)*81 + c] = sum_d x[n, h*64+d] * w_off[c, d]
// one block per token n.
// ============================================================
__global__ void __launch_bounds__(256) offset_kernel(
    const float* __restrict__ x, const float* __restrict__ w_off)
{
    __shared__ float xs[CDIM];
    __shared__ float wT[64 * 81];   // transposed: wT[k][c]
    const int n = blockIdx.x;
    const int tid = threadIdx.x;

    for (int i = tid; i < CDIM; i += 256) xs[i] = x[(size_t)n * CDIM + i];
    for (int i = tid; i < 81 * 64; i += 256) {
        int c = i >> 6, k = i & 63;
        wT[k * 81 + c] = w_off[i];
    }
    __syncthreads();

    for (int idx = tid; idx < NHEAD * 81; idx += 256) {
        const int h = idx / 81;
        const int c = idx - h * 81;
        const float* xh = xs + h * 64;
        float acc = 0.f;
#pragma unroll 8
        for (int k = 0; k < 64; k++) acc = fmaf(xh[k], wT[k * 81 + c], acc);
        g_off[((size_t)h * NTOK + n) * 81 + c] = acc;
    }
}

// ============================================================
// Fused deformable attention: one warp per (head, token).
// lane owns channels (2*lane, 2*lane+1).
//   logit[s] = scale * q . trilinear(k_map, pos(s)) + pos_emb(s)
//   out      = sum_s softmax(logit)_s * trilinear(v_map, pos(s))
// pos_emb(s) = q(z,y,x).rw[j] + q(z,x,y).rh[j] + q(x,z,y).rd[j], j = 15+s-x
// ============================================================
__global__ void __launch_bounds__(128) attn_kernel(
    const float* __restrict__ rel_d, const float* __restrict__ rel_h,
    const float* __restrict__ rel_w)
{
    const int warp = threadIdx.x >> 5;
    const int lane = threadIdx.x & 31;
    const int n = blockIdx.x * 4 + warp;
    const int h = blockIdx.y;
    const int z = n >> 8, y = (n >> 4) & 15, x = n & 15;
    const int c0 = lane << 1;

    const float* qkv = g_qkv;
    const float2 qa = *(const float2*)(qkv + (size_t)n * QKVW + h * 64 + c0);
    const int nzx = ((z << 4) + x) * 16 + y;   // token (z, x, y)
    const int nxz = ((x << 4) + z) * 16 + y;   // token (x, z, y)
    const float2 qb = *(const float2*)(qkv + (size_t)nzx * QKVW + h * 64 + c0);
    const float2 qc = *(const float2*)(qkv + (size_t)nxz * QKVW + h * 64 + c0);

    // lane l < 27 holds the 3 offset components of sample l
    const float* offp = g_off + ((size_t)h * NTOK + n) * 81;
    float oz = 0.f, oy = 0.f, ox = 0.f;
    if (lane < NSAMP) {
        oz = offp[lane * 3 + 0];
        oy = offp[lane * 3 + 1];
        ox = offp[lane * 3 + 2];
    }

    const float* kb = qkv + 512  + h * 64 + c0;   // k channels for this head/lane
    const float* vb = qkv + 1024 + h * 64 + c0;   // v channels

    float lg[NSAMP];

    // ---- pass 1: logits ----
#pragma unroll
    for (int s = 0; s < NSAMP; s++) {
        const float soz = __shfl_sync(0xffffffffu, oz, s);
        const float soy = __shfl_sync(0xffffffffu, oy, s);
        const float sox = __shfl_sync(0xffffffffu, ox, s);
        const float pz = (float)(z + s / 9 - 1) + soz;
        const float py = (float)(y + (s / 3) % 3 - 1) + soy;
        const float px = (float)(x + s % 3 - 1) + sox;
        const float fz = floorf(pz), fy = floorf(py), fx = floorf(px);
        const float wz = pz - fz, wy = py - fy, wx = px - fx;
        const int iz = (int)fz, iy = (int)fy, ix = (int)fx;

        float part = 0.f;
#pragma unroll
        for (int cz = 0; cz < 2; cz++) {
            const int zi = iz + cz;
            if ((unsigned)zi >= 16u) continue;
            const float wzc = cz ? wz : 1.f - wz;
#pragma unroll
            for (int cy = 0; cy < 2; cy++) {
                const int yi = iy + cy;
                if ((unsigned)yi >= 16u) continue;
                const float wyc = wzc * (cy ? wy : 1.f - wy);
#pragma unroll
                for (int cx = 0; cx < 2; cx++) {
                    const int xi = ix + cx;
                    if ((unsigned)xi >= 16u) continue;
                    const float w = wyc * (cx ? wx : 1.f - wx);
                    const int idx = (zi * 16 + yi) * 16 + xi;
                    const float2 kv = *(const float2*)(kb + (size_t)idx * QKVW);
                    part = fmaf(w, fmaf(kv.x, qa.x, kv.y * qa.y), part);
                }
            }
        }

        const int j = 15 + s - x;   // always in [0, 42)
        const float2 rwv = *(const float2*)(rel_w + j * 64 + c0);
        const float2 rhv = *(const float2*)(rel_h + j * 64 + c0);
        const float2 rdv = *(const float2*)(rel_d + j * 64 + c0);
        float val = 0.125f * part
                  + qa.x * rwv.x + qa.y * rwv.y
                  + qb.x * rhv.x + qb.y * rhv.y
                  + qc.x * rdv.x + qc.y * rdv.y;
#pragma unroll
        for (int o = 16; o > 0; o >>= 1)
            val += __shfl_xor_sync(0xffffffffu, val, o);
        lg[s] = val;
    }

    // ---- softmax over 27 (replicated across lanes) ----
    float mx = lg[0];
#pragma unroll
    for (int s = 1; s < NSAMP; s++) mx = fmaxf(mx, lg[s]);
    float ssum = 0.f;
#pragma unroll
    for (int s = 0; s < NSAMP; s++) { lg[s] = expf(lg[s] - mx); ssum += lg[s]; }
    const float inv = 1.f / ssum;

    // ---- pass 2: weighted v gather ----
    float a0 = 0.f, a1 = 0.f;
#pragma unroll
    for (int s = 0; s < NSAMP; s++) {
        const float soz = __shfl_sync(0xffffffffu, oz, s);
        const float soy = __shfl_sync(0xffffffffu, oy, s);
        const float sox = __shfl_sync(0xffffffffu, ox, s);
        const float pz = (float)(z + s / 9 - 1) + soz;
        const float py = (float)(y + (s / 3) % 3 - 1) + soy;
        const float px = (float)(x + s % 3 - 1) + sox;
        const float fz = floorf(pz), fy = floorf(py), fx = floorf(px);
        const float wz = pz - fz, wy = py - fy, wx = px - fx;
        const int iz = (int)fz, iy = (int)fy, ix = (int)fx;
        const float p = lg[s];
#pragma unroll
        for (int cz = 0; cz < 2; cz++) {
            const int zi = iz + cz;
            if ((unsigned)zi >= 16u) continue;
            const float wzc = p * (cz ? wz : 1.f - wz);
#pragma unroll
            for (int cy = 0; cy < 2; cy++) {
                const int yi = iy + cy;
                if ((unsigned)yi >= 16u) continue;
                const float wyc = wzc * (cy ? wy : 1.f - wy);
#pragma unroll
                for (int cx = 0; cx < 2; cx++) {
                    const int xi = ix + cx;
                    if ((unsigned)xi >= 16u) continue;
                    const float w = wyc * (cx ? wx : 1.f - wx);
                    const int idx = (zi * 16 + yi) * 16 + xi;
                    const float2 vv = *(const float2*)(vb + (size_t)idx * QKVW);
                    a0 = fmaf(w, vv.x, a0);
                    a1 = fmaf(w, vv.y, a1);
                }
            }
        }
    }

    float2 res;
    res.x = a0 * inv;
    res.y = a1 * inv;
    *(float2*)(g_ao + (size_t)n * CDIM + h * 64 + c0) = res;
}

// ============================================================
extern "C" void kernel_launch(void* const* d_in, const int* in_sizes, int n_in,
                              void* d_out, int out_size)
{
    const float* x      = (const float*)d_in[0];
    const float* w_qkv  = (const float*)d_in[1];
    const float* w_proj = (const float*)d_in[2];
    const float* b_proj = (const float*)d_in[3];
    const float* w_off  = (const float*)d_in[4];
    const float* rel_d  = (const float*)d_in[5];
    const float* rel_h  = (const float*)d_in[6];
    const float* rel_w  = (const float*)d_in[7];
    float* out = (float*)d_out;

    float *qkv_p, *ao_p;
    cudaGetSymbolAddress((void**)&qkv_p, g_qkv);
    cudaGetSymbolAddress((void**)&ao_p,  g_ao);

    // 1) qkv = x @ w_qkv^T          (4096 x 1536, K=512)
    sgemm_nt<<<dim3(QKVW / 128, NTOK / 128), 256>>>(x, w_qkv, nullptr, qkv_p,
                                                    NTOK, QKVW, CDIM);
    // 2) per-head deformable offsets
    offset_kernel<<<NTOK, 256>>>(x, w_off);

    // 3) fused deformable attention (+ relative position embedding + softmax)
    attn_kernel<<<dim3(NTOK / 4, NHEAD), 128>>>(rel_d, rel_h, rel_w);

    // 4) out = attn_out @ w_proj^T + b_proj   (4096 x 512, K=512)
    sgemm_nt<<<dim3(CDIM / 128, NTOK / 128), 256>>>(ao_p, w_proj, b_proj, out,
                                                    NTOK, CDIM, CDIM);
}